// round 2
// baseline (speedup 1.0000x reference)
#include <cuda_runtime.h>
#include <stdint.h>

#define S_LEN 4096
#define NBATCH 16
#define D_DIM 64
#define BQ 64
#define BK 64

// Bit-packed dropout keep-mask for all B*S*S = 2^28 positions: 2^23 words = 32 MB.
static __device__ uint32_t g_mask[1u << 23];

// ---------------------------------------------------------------------------
// Exact port of JAX threefry2x32 with key = threefry_seed(1) = (0, 1).
// ---------------------------------------------------------------------------
__device__ __forceinline__ uint2 threefry2x32_k01(uint32_t x0, uint32_t x1) {
    const uint32_t ks0 = 0u, ks1 = 1u, ks2 = 0x1BD11BDBu; // 0^1^0x1BD11BDA
    x0 += ks0; x1 += ks1;
#define TF_R(r) { x0 += x1; x1 = __funnelshift_l(x1, x1, (r)); x1 ^= x0; }
    TF_R(13) TF_R(15) TF_R(26) TF_R(6)
    x0 += ks1; x1 += ks2 + 1u;
    TF_R(17) TF_R(29) TF_R(16) TF_R(24)
    x0 += ks2; x1 += ks0 + 2u;
    TF_R(13) TF_R(15) TF_R(26) TF_R(6)
    x0 += ks0; x1 += ks1 + 3u;
    TF_R(17) TF_R(29) TF_R(16) TF_R(24)
    x0 += ks1; x1 += ks2 + 4u;
    TF_R(13) TF_R(15) TF_R(26) TF_R(6)
    x0 += ks2; x1 += ks0 + 5u;
#undef TF_R
    return make_uint2(x0, x1);
}

// JAX uniform: (bits >> 9) | 0x3f800000 viewed as float, minus 1.0  ->  [0,1)
__device__ __forceinline__ float jax_uniform(uint32_t bits) {
    return __uint_as_float((bits >> 9) | 0x3f800000u) - 1.0f;
}

// ---------------------------------------------------------------------------
// RNG kernel, threefry_partitionable=True semantics (modern JAX default):
// element i uses counter pair (hi32(i), lo32(i)) = (0, i) for N = 2^28,
// and the 32-bit output is x0_out ^ x1_out.
// Each thread produces 32 consecutive elements -> one packed mask word.
// ---------------------------------------------------------------------------
__global__ void __launch_bounds__(256) rng_mask_kernel(const float* __restrict__ p_drop_ptr) {
    const float keep_p = 1.0f - *p_drop_ptr;   // same f32 arithmetic as jnp 1.0 - p
    uint32_t t = blockIdx.x * 256u + threadIdx.x;   // t in [0, 2^23)
    uint32_t base = t << 5;
    uint32_t w = 0u;
#pragma unroll 8
    for (int j = 0; j < 32; ++j) {
        uint2 o = threefry2x32_k01(0u, base + (uint32_t)j);
        uint32_t bits = o.x ^ o.y;
        w |= (jax_uniform(bits) < keep_p ? 1u : 0u) << j;
    }
    g_mask[t] = w;
}

// ---------------------------------------------------------------------------
// Flash attention, fp32 CUDA cores.
// CTA: 128 threads = 16x8 grid. Thread (tr,tc) owns 4 q-rows x 8 k-cols of the
// 64x64 score tile, and 4 q-rows x 8 d-cols of the output tile.
// SMEM: Qt [d][q] (Q pre-scaled by 1/inv_scale), KP = union of Kt [d][k] and
// P [k][q] (rotation-swizzled), Vs [k][d]. 48 KB static total.
// ---------------------------------------------------------------------------
__global__ void __launch_bounds__(128) attn_kernel(
    const float* __restrict__ Q, const float* __restrict__ K,
    const float* __restrict__ V, const float* __restrict__ pd_ptr,
    const float* __restrict__ is_ptr, float* __restrict__ O)
{
    __shared__ float Qt[BQ * D_DIM];
    __shared__ float KP[BK * D_DIM];
    __shared__ float Vs[BK * D_DIM];

    const int tid = threadIdx.x;
    const int b   = blockIdx.y;
    const int qt  = blockIdx.x;
    const int tr  = tid >> 3;       // 0..15
    const int tc  = tid & 7;        // 0..7
    const int q0  = tr << 2;        // local q base (4 rows)
    const int c0  = tc << 3;        // local k base (score) / d base (output)

    const float rscale   = 1.0f / (*is_ptr);
    const float p_drop   = *pd_ptr;
    const float inv_keep = 1.0f / (1.0f - p_drop);

    // Load Q tile transposed, pre-scaled (1/8 is exact, so identical rounding).
    const float* Qg = Q + ((size_t)(b * S_LEN + qt * BQ)) * D_DIM;
    for (int idx = tid; idx < BQ * (D_DIM / 4); idx += 128) {
        int row = idx & 63;
        int c4  = (idx >> 6) << 2;
        float4 v = *(const float4*)(Qg + row * D_DIM + c4);
        Qt[(c4 + 0) * BQ + row] = v.x * rscale;
        Qt[(c4 + 1) * BQ + row] = v.y * rscale;
        Qt[(c4 + 2) * BQ + row] = v.z * rscale;
        Qt[(c4 + 3) * BQ + row] = v.w * rscale;
    }

    float acc[4][8];
    float m[4], l[4];
#pragma unroll
    for (int i = 0; i < 4; ++i) {
        m[i] = -1e30f; l[i] = 0.f;
#pragma unroll
        for (int j = 0; j < 8; ++j) acc[i][j] = 0.f;
    }

    const uint32_t qrow_base = (uint32_t)(b * S_LEN + qt * BQ);

    for (int kt = 0; kt < S_LEN / BK; ++kt) {
        __syncthreads();  // previous P-GEMM done (and Q tile visible on kt==0)
        const float* Kg = K + ((size_t)(b * S_LEN + kt * BK)) * D_DIM;
        const float* Vg = V + ((size_t)(b * S_LEN + kt * BK)) * D_DIM;

        // K tile, transposed into KP[d][k]. Row-per-lane mapping keeps the
        // scattered smem stores conflict-free (K/V tiles are L2-hot: each is
        // re-read by all 64 q-tile CTAs of this batch).
        for (int idx = tid; idx < BK * (D_DIM / 4); idx += 128) {
            int row = idx & 63;
            int c4  = (idx >> 6) << 2;
            float4 v = *(const float4*)(Kg + row * D_DIM + c4);
            KP[(c4 + 0) * BK + row] = v.x;
            KP[(c4 + 1) * BK + row] = v.y;
            KP[(c4 + 2) * BK + row] = v.z;
            KP[(c4 + 3) * BK + row] = v.w;
        }
        // V tile, direct coalesced copy.
        for (int idx = tid; idx < BK * (D_DIM / 4); idx += 128) {
            int row = idx >> 4;
            int c4  = (idx & 15) << 2;
            *(float4*)&Vs[row * D_DIM + c4] = *(const float4*)(Vg + row * D_DIM + c4);
        }
        __syncthreads();

        // ---- S = (Q * rscale) @ K^T ----
        float s[4][8];
#pragma unroll
        for (int i = 0; i < 4; ++i)
#pragma unroll
            for (int j = 0; j < 8; ++j) s[i][j] = 0.f;

#pragma unroll 8
        for (int d = 0; d < D_DIM; ++d) {
            float4 a  = *(const float4*)&Qt[d * BQ + q0];
            float4 b0 = *(const float4*)&KP[d * BK + c0];
            float4 b1 = *(const float4*)&KP[d * BK + c0 + 4];
            float av[4] = {a.x, a.y, a.z, a.w};
            float bv[8] = {b0.x, b0.y, b0.z, b0.w, b1.x, b1.y, b1.z, b1.w};
#pragma unroll
            for (int i = 0; i < 4; ++i)
#pragma unroll
                for (int j = 0; j < 8; ++j) s[i][j] += av[i] * bv[j];
        }

        // ---- online softmax (row groups = 8 consecutive lanes) ----
        float corr[4];
#pragma unroll
        for (int i = 0; i < 4; ++i) {
            float v = s[i][0];
#pragma unroll
            for (int j = 1; j < 8; ++j) v = fmaxf(v, s[i][j]);
#pragma unroll
            for (int off = 1; off < 8; off <<= 1)
                v = fmaxf(v, __shfl_xor_sync(0xffffffffu, v, off));
            float mn = fmaxf(m[i], v);
            corr[i] = __expf(m[i] - mn);
            m[i] = mn;
        }
#pragma unroll
        for (int i = 0; i < 4; ++i) {
            float sum = 0.f;
#pragma unroll
            for (int j = 0; j < 8; ++j) {
                s[i][j] = __expf(s[i][j] - m[i]);
                sum += s[i][j];
            }
#pragma unroll
            for (int off = 1; off < 8; off <<= 1)
                sum += __shfl_xor_sync(0xffffffffu, sum, off);
            l[i] = l[i] * corr[i] + sum;   // normalizer uses UN-dropped probs
#pragma unroll
            for (int j = 0; j < 8; ++j) acc[i][j] *= corr[i];
        }

        __syncthreads();  // all threads done reading KP as Kt

        // ---- dropout mask + store P into KP[k][q] with rotation swizzle ----
#pragma unroll
        for (int i = 0; i < 4; ++i) {
            uint32_t flat = (qrow_base + (uint32_t)(q0 + i)) * (uint32_t)S_LEN
                          + (uint32_t)(kt * BK + c0);
            uint32_t bits = (g_mask[flat >> 5] >> (flat & 31u)) & 0xffu;
#pragma unroll
            for (int j = 0; j < 8; ++j) {
                int kk = c0 + j;
                float pv = ((bits >> j) & 1u) ? s[i][j] : 0.f;
                KP[kk * BQ + ((q0 + i + kk) & 63)] = pv;
            }
        }
        __syncthreads();

        // ---- O += P @ V ----
#pragma unroll 4
        for (int kk = 0; kk < BK; ++kk) {
            float4 v0 = *(const float4*)&Vs[kk * D_DIM + c0];
            float4 v1 = *(const float4*)&Vs[kk * D_DIM + c0 + 4];
            float vv[8] = {v0.x, v0.y, v0.z, v0.w, v1.x, v1.y, v1.z, v1.w};
            float pv[4];
#pragma unroll
            for (int i = 0; i < 4; ++i)
                pv[i] = KP[kk * BQ + ((q0 + i + kk) & 63)];
#pragma unroll
            for (int i = 0; i < 4; ++i)
#pragma unroll
                for (int j = 0; j < 8; ++j) acc[i][j] += pv[i] * vv[j];
        }
    }

    // ---- epilogue: O = acc / l * 1/(1-p) ----
    float* Og = O + ((size_t)(b * S_LEN + qt * BQ)) * D_DIM;
#pragma unroll
    for (int i = 0; i < 4; ++i) {
        float r = inv_keep / l[i];
        float4 o0 = make_float4(acc[i][0] * r, acc[i][1] * r, acc[i][2] * r, acc[i][3] * r);
        float4 o1 = make_float4(acc[i][4] * r, acc[i][5] * r, acc[i][6] * r, acc[i][7] * r);
        *(float4*)(Og + (size_t)(q0 + i) * D_DIM + c0)     = o0;
        *(float4*)(Og + (size_t)(q0 + i) * D_DIM + c0 + 4) = o1;
    }
}

extern "C" void kernel_launch(void* const* d_in, const int* in_sizes, int n_in,
                              void* d_out, int out_size) {
    (void)in_sizes; (void)n_in; (void)out_size;
    const float* Q  = (const float*)d_in[0];
    const float* K  = (const float*)d_in[1];
    const float* V  = (const float*)d_in[2];
    const float* pd = (const float*)d_in[3];
    const float* is = (const float*)d_in[4];
    float* O = (float*)d_out;

    rng_mask_kernel<<<(1u << 23) / 256, 256>>>(pd);
    attn_kernel<<<dim3(S_LEN / BQ, NBATCH), 128>>>(Q, K, V, pd, is, O);
}